// round 12
// baseline (speedup 1.0000x reference)
#include <cuda_runtime.h>
#include <cuda_bf16.h>
#include <cstdint>

#define Bn 2
#define Sn 2048
#define Dn 1024
#define Hn 16
#define HDn 64
#define Mn (Bn*Sn)

// Scratch (allocation-free rule: device globals)
__device__ float g_att[Mn*Dn];
__device__ float g_xr[Mn*Dn];                 // tf32-rounded x
__device__ float g_wqr[Dn*Dn], g_wkr[Dn*Dn], g_wvr[Dn*Dn], g_wor[Dn*Dn];
__device__ float g_cos[Sn*32];
__device__ float g_sin[Sn*32];
__device__ __nv_bfloat16 g_qh[Mn*Dn], g_ql[Mn*Dn];
__device__ __nv_bfloat16 g_kh[Mn*Dn], g_kl[Mn*Dn];
__device__ __nv_bfloat16 g_vh[Mn*Dn], g_vl[Mn*Dn];

// ---------------------------------------------------------------------------
__device__ __forceinline__ void cpa16(uint32_t dst, const void* src) {
    asm volatile("cp.async.cg.shared.global [%0], [%1], 16;" :: "r"(dst), "l"(src));
}
#define CP_COMMIT() asm volatile("cp.async.commit_group;" ::: "memory")
#define CP_WAIT(n)  asm volatile("cp.async.wait_group %0;" :: "n"(n) : "memory")

__device__ __forceinline__ uint32_t smem_u32(const void* p) {
    uint32_t a;
    asm("{ .reg .u64 t; cvta.to.shared.u64 t, %1; cvt.u32.u64 %0, t; }"
        : "=r"(a) : "l"(p));
    return a;
}

__device__ __forceinline__ float tf32r(float x) {
    float y;
    asm("cvt.rna.tf32.f32 %0, %1;" : "=f"(y) : "f"(x));
    return y;
}

// single-MUFU exp2
__device__ __forceinline__ float ex2(float x) {
    float y;
    asm("ex2.approx.f32 %0, %1;" : "=f"(y) : "f"(x));
    return y;
}

// exact-residual bf16 hi/lo split of a float pair, 6 instructions.
__device__ __forceinline__ void split2(float a, float b,
                                       uint32_t& hh, uint32_t& ll) {
    asm("cvt.rn.bf16x2.f32 %0, %1, %2;" : "=r"(hh) : "f"(b), "f"(a));
    float ha = __uint_as_float(hh << 16);
    float hb = __uint_as_float(hh & 0xFFFF0000u);
    float la = a - ha;
    float lb = b - hb;
    asm("cvt.rn.bf16x2.f32 %0, %1, %2;" : "=r"(ll) : "f"(lb), "f"(la));
}

// mma m16n8k8 tf32 -> f32
#define MMA_TF32(c, a0, a1, a2, a3, b0, b1)                                   \
    asm volatile(                                                             \
        "mma.sync.aligned.m16n8k8.row.col.f32.tf32.tf32.f32 "                 \
        "{%0,%1,%2,%3},{%4,%5,%6,%7},{%8,%9},{%0,%1,%2,%3};"                  \
        : "+f"((c)[0]), "+f"((c)[1]), "+f"((c)[2]), "+f"((c)[3])              \
        : "r"(a0), "r"(a1), "r"(a2), "r"(a3), "r"(b0), "r"(b1))

// mma m16n8k16 bf16 -> f32
#define MMA16816(c, a0, a1, a2, a3, b0, b1)                                   \
    asm volatile(                                                             \
        "mma.sync.aligned.m16n8k16.row.col.f32.bf16.bf16.f32 "                \
        "{%0,%1,%2,%3}, {%4,%5,%6,%7}, {%8,%9}, {%0,%1,%2,%3};"               \
        : "+f"((c)[0]), "+f"((c)[1]), "+f"((c)[2]), "+f"((c)[3])              \
        : "r"(a0), "r"(a1), "r"(a2), "r"(a3), "r"(b0), "r"(b1))

#define LDSM_X4(d0,d1,d2,d3,a)                                                \
    asm volatile("ldmatrix.sync.aligned.m8n8.x4.shared.b16 {%0,%1,%2,%3}, [%4];" \
        : "=r"(d0), "=r"(d1), "=r"(d2), "=r"(d3) : "r"(a))
#define LDSM_X4_T(d0,d1,d2,d3,a)                                              \
    asm volatile("ldmatrix.sync.aligned.m8n8.x4.trans.shared.b16 {%0,%1,%2,%3}, [%4];" \
        : "=r"(d0), "=r"(d1), "=r"(d2), "=r"(d3) : "r"(a))

#define ONESBF 0x3F803F80u

// ---------------------------------------------------------------------------
// Fused prep: RoPE tables + tf32 pre-rounding of x and the four W matrices.
// ---------------------------------------------------------------------------
__global__ void prep_kernel(const float* __restrict__ x,
                            const float* __restrict__ wq,
                            const float* __restrict__ wk,
                            const float* __restrict__ wv,
                            const float* __restrict__ wo)
{
    int gidx = blockIdx.x * 256 + threadIdx.x;

    if (gidx < Sn * 32) {        // RoPE tables
        int pos = gidx >> 5;
        int i   = gidx & 31;
        float inv = exp2f(-(float)i * 0.4152410118609203f);  // log2(10000)/32
        float ang = (float)pos * inv;
        float s, c;
        sincosf(ang, &s, &c);
        g_cos[gidx] = c;
        g_sin[gidx] = s;
    }

    int i4 = gidx * 4;
    const float* src;
    float* dst;
    int off;
    if (i4 < Mn * Dn) {
        src = x; dst = g_xr; off = i4;
    } else {
        int j = i4 - Mn * Dn;
        int w = j >> 20;
        off = j & ((1 << 20) - 1);
        src = (w == 0) ? wq : (w == 1) ? wk : (w == 2) ? wv : wo;
        dst = (w == 0) ? g_wqr : (w == 1) ? g_wkr : (w == 2) ? g_wvr : g_wor;
    }
    float4 v = *(const float4*)(src + off);
    v.x = tf32r(v.x); v.y = tf32r(v.y); v.z = tf32r(v.z); v.w = tf32r(v.w);
    *(float4*)(dst + off) = v;
}

// ---------------------------------------------------------------------------
// Raw-mma tf32 GEMM: 256x128 CTA tile (halves L2 traffic per MAC vs 128x128),
// 1 CTA/SM, warp tile 64x64 (4m x 2n warps), BK=32, 3-stage cp.async.
// Per-chunk L2 demand: 48KB / 2048 tensor-cyc = 24 B/cyc/SM < 42.5 ceiling.
// ---------------------------------------------------------------------------
#define ASTAGE 36864                 // A: 256 rows x 144 B
#define WSTAGE 18432                 // W: 128 rows x 144 B
#define GSTG   (ASTAGE + WSTAGE)     // 55296
#define GSMEM  (3 * GSTG)            // 165888 bytes

// Q scale with log2(e) folded in (softmax done in base 2)
#define QSCALE 0.18033688011112043f

template<int MODE>
__global__ void __launch_bounds__(256, 1) gemm_mma(
    const float* __restrict__ A,
    const float* __restrict__ W0, const float* __restrict__ W1,
    const float* __restrict__ W2,
    const float* __restrict__ b0p, const float* __restrict__ b1p,
    const float* __restrict__ b2p,
    float* __restrict__ C)
{
    extern __shared__ float smem[];
    const uint32_t sb = smem_u32(smem);
    const int tid = threadIdx.x;
    const int wid = tid >> 5, lane = tid & 31;
    const int g = lane >> 2, tig = lane & 3;
    const int wm = wid & 3, wn = wid >> 2;
    const int m0 = blockIdx.y * 256;

    int wsel = 0, n0;
    const float* W;
    const float* bias;
    if (MODE == 1) {
        wsel = blockIdx.x >> 3;
        n0 = (blockIdx.x & 7) * 128;
        W    = (wsel == 0) ? W0 : (wsel == 1) ? W1 : W2;
        bias = (wsel == 0) ? b0p : (wsel == 1) ? b1p : b2p;
    } else {
        n0 = blockIdx.x * 128;
        W = W0; bias = b0p;
    }

    const int l8 = lane & 7;
    const int lh = (lane >> 3) & 1;
    const int lq = (lane >> 4) & 1;
    uint32_t aoff[4];
    #pragma unroll
    for (int mi = 0; mi < 4; ++mi)
        aoff[mi] = (uint32_t)((wm * 64 + mi * 16 + lh * 8 + l8) * 144 + lq * 16);
    uint32_t boff[4];
    #pragma unroll
    for (int j = 0; j < 4; ++j)
        boff[j] = (uint32_t)(ASTAGE +
                  (wn * 64 + (2 * j + lq) * 8 + l8) * 144 + lh * 16);

    auto loadChunk = [&](int c) {
        const uint32_t abase = sb + (uint32_t)(c % 3) * GSTG;
        const uint32_t wbase = abase + ASTAGE;
        const float* Ab = A + (size_t)m0 * Dn + c * 32;
        const float* Wb = W + (size_t)n0 * Dn + c * 32;
        #pragma unroll
        for (int i = 0; i < 12; ++i) {
            int task = tid + i * 256;        // 3072 tasks: 2048 A + 1024 W
            int row = task >> 3;
            int q   = task & 7;
            if (row < 256) {
                cpa16(abase + (uint32_t)(row * 144 + q * 16),
                      Ab + (size_t)row * Dn + q * 4);
            } else {
                cpa16(wbase + (uint32_t)((row - 256) * 144 + q * 16),
                      Wb + (size_t)(row - 256) * Dn + q * 4);
            }
        }
        CP_COMMIT();
    };

    float acc[4][8][4];
    #pragma unroll
    for (int mi = 0; mi < 4; ++mi)
        #pragma unroll
        for (int nj = 0; nj < 8; ++nj)
            #pragma unroll
            for (int e = 0; e < 4; ++e) acc[mi][nj][e] = 0.0f;

    loadChunk(0); loadChunk(1);

    for (int c = 0; c < 32; ++c) {
        if (c + 1 < 32) CP_WAIT(1);
        else            CP_WAIT(0);
        __syncthreads();
        if (c + 2 < 32) loadChunk(c + 2);

        const uint32_t stb = sb + (uint32_t)(c % 3) * GSTG;

        #pragma unroll
        for (int k8 = 0; k8 < 4; ++k8) {
            const uint32_t kb = (uint32_t)k8 * 32;
            uint32_t a[4][4];
            #pragma unroll
            for (int mi = 0; mi < 4; ++mi)
                LDSM_X4(a[mi][0], a[mi][1], a[mi][2], a[mi][3],
                        stb + aoff[mi] + kb);
            #pragma unroll
            for (int j = 0; j < 4; ++j) {
                uint32_t b00, b01, b10, b11;
                LDSM_X4(b00, b01, b10, b11, stb + boff[j] + kb);
                #pragma unroll
                for (int mi = 0; mi < 4; ++mi) {
                    MMA_TF32(acc[mi][2*j],   a[mi][0], a[mi][1], a[mi][2], a[mi][3], b00, b01);
                    MMA_TF32(acc[mi][2*j+1], a[mi][0], a[mi][1], a[mi][2], a[mi][3], b10, b11);
                }
            }
        }
    }

    #pragma unroll
    for (int mi = 0; mi < 4; ++mi) {
        #pragma unroll
        for (int nj = 0; nj < 8; ++nj) {
            const int col_l = wn * 64 + nj * 8 + 2 * tig;
            #pragma unroll
            for (int e2 = 0; e2 < 2; ++e2) {
                const int row = m0 + wm * 64 + mi * 16 + g + e2 * 8;
                float v0 = acc[mi][nj][e2 * 2 + 0] + __ldg(&bias[col_l]);
                float v1 = acc[mi][nj][e2 * 2 + 1] + __ldg(&bias[col_l + 1]);
                if (MODE == 0) {
                    *(float2*)(C + (size_t)row * Dn + n0 + col_l) =
                        make_float2(v0, v1);
                } else {
                    if (wsel < 2) {
                        const int pos = row & (Sn - 1);
                        const int i0 = (col_l & 63) >> 1;
                        float cc = g_cos[pos * 32 + i0];
                        float ss = g_sin[pos * 32 + i0];
                        float o0 = v0 * cc - v1 * ss;
                        float o1 = v0 * ss + v1 * cc;
                        v0 = o0; v1 = o1;
                    }
                    if (wsel == 0) { v0 *= QSCALE; v1 *= QSCALE; }
                    uint32_t hh, ll;
                    split2(v0, v1, hh, ll);
                    const size_t idx = (size_t)row * Dn + n0 + col_l;
                    __nv_bfloat16* dh = (wsel == 0) ? g_qh : (wsel == 1) ? g_kh : g_vh;
                    __nv_bfloat16* dl = (wsel == 0) ? g_ql : (wsel == 1) ? g_kl : g_vl;
                    *(uint32_t*)(dh + idx) = hh;
                    *(uint32_t*)(dl + idx) = ll;
                }
            }
        }
    }
}

// ---------------------------------------------------------------------------
// Flash attention v6: 3-stage pipeline + mma row-sum (unchanged from R11).
// ---------------------------------------------------------------------------
#define ASTG 36864
#define ATT_SMEM (3 * ASTG)         // 110592

__global__ void __launch_bounds__(256, 2) attn6(const int* __restrict__ eff,
                                                float* __restrict__ Outp)
{
    extern __shared__ char sm[];
    const uint32_t sb = smem_u32(sm);

    const int t = threadIdx.x, w = t >> 5, lane = t & 31;
    const int g = lane >> 2, tig = lane & 3;
    const int part = lane >> 3, r8 = lane & 7;
    const int q0 = ((int)gridDim.x - 1 - (int)blockIdx.x) * 128;
    const int h = blockIdx.y, b = blockIdx.z;
    const int kend = Sn - eff[b];
    const size_t bofs = (size_t)b * Sn * Dn + h * HDn;

    const int row0 = q0 + w * 16 + g;
    const int row1 = row0 + 8;

    const uint32_t kbase = sb + (part < 2 ? 0u : 9216u)
                         + (uint32_t)r8 * 144 + (uint32_t)(part & 1) * 16;
    const uint32_t vbase = sb + 18432u + (part < 2 ? 0u : 9216u)
                         + (uint32_t)(part & 1) * 1152 + (uint32_t)r8 * 144;

    // --- Q fragments (hi/lo) in registers ---
    uint32_t qhf[4][4], qlf[4][4];
    {
        const __nv_bfloat16* bh = g_qh + bofs + (size_t)row0 * Dn;
        const __nv_bfloat16* bl = g_ql + bofs + (size_t)row0 * Dn;
        #pragma unroll
        for (int ks = 0; ks < 4; ++ks) {
            int d0 = ks * 16 + 2 * tig;
            qhf[ks][0] = *(const uint32_t*)(bh + d0);
            qhf[ks][1] = *(const uint32_t*)(bh + 8 * (size_t)Dn + d0);
            qhf[ks][2] = *(const uint32_t*)(bh + d0 + 8);
            qhf[ks][3] = *(const uint32_t*)(bh + 8 * (size_t)Dn + d0 + 8);
            qlf[ks][0] = *(const uint32_t*)(bl + d0);
            qlf[ks][1] = *(const uint32_t*)(bl + 8 * (size_t)Dn + d0);
            qlf[ks][2] = *(const uint32_t*)(bl + d0 + 8);
            qlf[ks][3] = *(const uint32_t*)(bl + 8 * (size_t)Dn + d0 + 8);
        }
    }

    float oc[8][4];
    #pragma unroll
    for (int n = 0; n < 8; ++n) { oc[n][0]=0.f; oc[n][1]=0.f; oc[n][2]=0.f; oc[n][3]=0.f; }
    float m0r = -1e30f, m1r = -1e30f, l0r = 0.f, l1r = 0.f;

    const int klimit = min(q0 + 128, kend);
    const int nt = (klimit + 63) >> 6;

    auto loadTile = [&](int tile) {
        const uint32_t base = sb + (uint32_t)(tile % 3) * ASTG;
        const size_t go = bofs + (size_t)(tile * 64) * Dn;
        const __nv_bfloat16* srcs[4] = { g_kh + go, g_kl + go, g_vh + go, g_vl + go };
        #pragma unroll
        for (int i = 0; i < 8; ++i) {
            const int arr = i >> 1;
            const int c2 = t + (i & 1) * 256;     // 0..511
            const int kr = c2 >> 3, q = c2 & 7;
            cpa16(base + (uint32_t)arr * 9216 + (uint32_t)kr * 144 + (uint32_t)q * 16,
                  srcs[arr] + (size_t)kr * Dn + q * 8);
        }
        CP_COMMIT();
    };

    loadTile(0);
    if (nt > 1) loadTile(1);

    for (int tile = 0; tile < nt; ++tile) {
        const int j0 = tile * 64;
        if (tile + 1 < nt) CP_WAIT(1);
        else               CP_WAIT(0);
        __syncthreads();
        if (tile + 2 < nt) loadTile(tile + 2);

        const uint32_t stoff = (uint32_t)(tile % 3) * ASTG;

        // --- S = Q K^T (bf16x3) via ldmatrix ---
        float sc[8][4];
        #pragma unroll
        for (int n = 0; n < 8; ++n) {
            float c[4] = {0.f, 0.f, 0.f, 0.f};
            const uint32_t ka = kbase + stoff + (uint32_t)n * 1152;
            #pragma unroll
            for (int ks = 0; ks < 4; ++ks) {
                uint32_t b0h, b1h, b0l, b1l;
                LDSM_X4(b0h, b1h, b0l, b1l, ka + (uint32_t)ks * 32);
                MMA16816(c, qhf[ks][0], qhf[ks][1], qhf[ks][2], qhf[ks][3], b0h, b1h);
                MMA16816(c, qhf[ks][0], qhf[ks][1], qhf[ks][2], qhf[ks][3], b0l, b1l);
                MMA16816(c, qlf[ks][0], qlf[ks][1], qlf[ks][2], qlf[ks][3], b0h, b1h);
            }
            sc[n][0] = c[0]; sc[n][1] = c[1]; sc[n][2] = c[2]; sc[n][3] = c[3];
        }

        // --- mask (skipped for interior tiles; warp-uniform test) ---
        const bool interior = (j0 + 63 <= q0 + w * 16) && (j0 + 64 <= kend);
        if (!interior) {
            #pragma unroll
            for (int n = 0; n < 8; ++n) {
                int col = j0 + n * 8 + 2 * tig;
                sc[n][0] = (col     <= row0 && col     < kend) ? sc[n][0] : -1e30f;
                sc[n][1] = (col + 1 <= row0 && col + 1 < kend) ? sc[n][1] : -1e30f;
                sc[n][2] = (col     <= row1 && col     < kend) ? sc[n][2] : -1e30f;
                sc[n][3] = (col + 1 <= row1 && col + 1 < kend) ? sc[n][3] : -1e30f;
            }
        }

        // --- register online softmax (base-2); row max via shfl ---
        float mx0 = -1e30f, mx1 = -1e30f;
        #pragma unroll
        for (int n = 0; n < 8; ++n) {
            mx0 = fmaxf(mx0, fmaxf(sc[n][0], sc[n][1]));
            mx1 = fmaxf(mx1, fmaxf(sc[n][2], sc[n][3]));
        }
        mx0 = fmaxf(mx0, __shfl_xor_sync(0xffffffffu, mx0, 1));
        mx0 = fmaxf(mx0, __shfl_xor_sync(0xffffffffu, mx0, 2));
        mx1 = fmaxf(mx1, __shfl_xor_sync(0xffffffffu, mx1, 1));
        mx1 = fmaxf(mx1, __shfl_xor_sync(0xffffffffu, mx1, 2));

        float nm0 = fmaxf(m0r, mx0), nm1 = fmaxf(m1r, mx1);
        float al0 = ex2(m0r - nm0), al1 = ex2(m1r - nm1);
        m0r = nm0; m1r = nm1;

        #pragma unroll
        for (int n = 0; n < 8; ++n) {
            sc[n][0] = ex2(sc[n][0] - nm0);
            sc[n][1] = ex2(sc[n][1] - nm0);
            sc[n][2] = ex2(sc[n][2] - nm1);
            sc[n][3] = ex2(sc[n][3] - nm1);
        }

        #pragma unroll
        for (int n = 0; n < 8; ++n) {
            oc[n][0] *= al0; oc[n][1] *= al0;
            oc[n][2] *= al1; oc[n][3] *= al1;
        }

        // --- O += P V (bf16x3) + row-sum via ones-column mma ---
        float ps[4] = {0.f, 0.f, 0.f, 0.f};
        #pragma unroll
        for (int ks = 0; ks < 4; ++ks) {
            uint32_t a0h, a1h, a2h, a3h, a0l, a1l, a2l, a3l;
            split2(sc[2*ks][0],   sc[2*ks][1],   a0h, a0l);
            split2(sc[2*ks][2],   sc[2*ks][3],   a1h, a1l);
            split2(sc[2*ks+1][0], sc[2*ks+1][1], a2h, a2l);
            split2(sc[2*ks+1][2], sc[2*ks+1][3], a3h, a3l);
            MMA16816(ps, a0h, a1h, a2h, a3h, ONESBF, ONESBF);
            MMA16816(ps, a0l, a1l, a2l, a3l, ONESBF, ONESBF);
            const uint32_t va = vbase + stoff + (uint32_t)ks * 2304;
            #pragma unroll
            for (int n = 0; n < 8; ++n) {
                uint32_t b0h, b1h, b0l, b1l;
                LDSM_X4_T(b0h, b1h, b0l, b1l, va + (uint32_t)n * 16);
                MMA16816(oc[n], a0h, a1h, a2h, a3h, b0h, b1h);
                MMA16816(oc[n], a0h, a1h, a2h, a3h, b0l, b1l);
                MMA16816(oc[n], a0l, a1l, a2l, a3l, b0h, b1h);
            }
        }
        l0r = l0r * al0 + ps[0];
        l1r = l1r * al1 + ps[2];
    }

    // --- epilogue: normalize + tf32-round + store ---
    float invA = 1.f / l0r;
    float invB = 1.f / l1r;
    float* Ob = Outp + bofs + (size_t)row0 * Dn;
    #pragma unroll
    for (int n = 0; n < 8; ++n) {
        int cc = n * 8 + 2 * tig;
        *(float2*)&Ob[cc] =
            make_float2(tf32r(oc[n][0] * invA), tf32r(oc[n][1] * invA));
        *(float2*)(Ob + 8 * (size_t)Dn + cc) =
            make_float2(tf32r(oc[n][2] * invB), tf32r(oc[n][3] * invB));
    }
}

// ---------------------------------------------------------------------------
extern "C" void kernel_launch(void* const* d_in, const int* in_sizes, int n_in,
                              void* d_out, int out_size)
{
    const float* x   = (const float*)d_in[0];
    const int*   eff = (const int*)d_in[1];
    const float* Wq  = (const float*)d_in[2];
    const float* bq  = (const float*)d_in[3];
    const float* Wk  = (const float*)d_in[4];
    const float* bk  = (const float*)d_in[5];
    const float* Wv  = (const float*)d_in[6];
    const float* bv  = (const float*)d_in[7];
    const float* Wo  = (const float*)d_in[8];
    const float* bo  = (const float*)d_in[9];
    float* out = (float*)d_out;

    float *att, *xr, *wqr, *wkr, *wvr, *wor;
    cudaGetSymbolAddress((void**)&att, g_att);
    cudaGetSymbolAddress((void**)&xr,  g_xr);
    cudaGetSymbolAddress((void**)&wqr, g_wqr);
    cudaGetSymbolAddress((void**)&wkr, g_wkr);
    cudaGetSymbolAddress((void**)&wvr, g_wvr);
    cudaGetSymbolAddress((void**)&wor, g_wor);

    cudaFuncSetAttribute(gemm_mma<0>,
                         cudaFuncAttributeMaxDynamicSharedMemorySize, GSMEM);
    cudaFuncSetAttribute(gemm_mma<1>,
                         cudaFuncAttributeMaxDynamicSharedMemorySize, GSMEM);
    cudaFuncSetAttribute(attn6,
                         cudaFuncAttributeMaxDynamicSharedMemorySize, ATT_SMEM);

    prep_kernel<<<(Mn * Dn + 4 * Dn * Dn) / 1024, 256>>>(x, Wq, Wk, Wv, Wo);

    // fused QKV projection (3 x 8 n-tiles x 16 m-tiles of 256 rows)
    gemm_mma<1><<<dim3(24, 16), 256, GSMEM>>>(xr, wqr, wkr, wvr,
                                              bq, bk, bv, nullptr);

    attn6<<<dim3(Sn / 128, Hn, Bn), 256, ATT_SMEM>>>(eff, att);

    // O projection
    gemm_mma<0><<<dim3(8, 16), 256, GSMEM>>>(att, wor, nullptr, nullptr,
                                             bo, nullptr, nullptr, out);
}

// round 14
// speedup vs baseline: 1.0633x; 1.0633x over previous
#include <cuda_runtime.h>
#include <cuda_bf16.h>
#include <cstdint>

#define Bn 2
#define Sn 2048
#define Dn 1024
#define Hn 16
#define HDn 64
#define Mn (Bn*Sn)

// Scratch (allocation-free rule: device globals)
__device__ float g_att[Mn*Dn];
__device__ float g_xr[Mn*Dn];                 // tf32-rounded x
__device__ float g_wqr[Dn*Dn], g_wkr[Dn*Dn], g_wvr[Dn*Dn], g_wor[Dn*Dn];
__device__ float g_cos[Sn*32];
__device__ float g_sin[Sn*32];
__device__ __nv_bfloat16 g_qh[Mn*Dn], g_ql[Mn*Dn];
__device__ __nv_bfloat16 g_kh[Mn*Dn], g_kl[Mn*Dn];
__device__ __nv_bfloat16 g_vh[Mn*Dn], g_vl[Mn*Dn];

// ---------------------------------------------------------------------------
__device__ __forceinline__ void cpa16(uint32_t dst, const void* src) {
    asm volatile("cp.async.cg.shared.global [%0], [%1], 16;" :: "r"(dst), "l"(src));
}
#define CP_COMMIT() asm volatile("cp.async.commit_group;" ::: "memory")
#define CP_WAIT(n)  asm volatile("cp.async.wait_group %0;" :: "n"(n) : "memory")

__device__ __forceinline__ uint32_t smem_u32(const void* p) {
    uint32_t a;
    asm("{ .reg .u64 t; cvta.to.shared.u64 t, %1; cvt.u32.u64 %0, t; }"
        : "=r"(a) : "l"(p));
    return a;
}

__device__ __forceinline__ float tf32r(float x) {
    float y;
    asm("cvt.rna.tf32.f32 %0, %1;" : "=f"(y) : "f"(x));
    return y;
}

// single-MUFU exp2
__device__ __forceinline__ float ex2(float x) {
    float y;
    asm("ex2.approx.f32 %0, %1;" : "=f"(y) : "f"(x));
    return y;
}

// exact-residual bf16 hi/lo split of a float pair, 6 instructions.
__device__ __forceinline__ void split2(float a, float b,
                                       uint32_t& hh, uint32_t& ll) {
    asm("cvt.rn.bf16x2.f32 %0, %1, %2;" : "=r"(hh) : "f"(b), "f"(a));
    float ha = __uint_as_float(hh << 16);
    float hb = __uint_as_float(hh & 0xFFFF0000u);
    float la = a - ha;
    float lb = b - hb;
    asm("cvt.rn.bf16x2.f32 %0, %1, %2;" : "=r"(ll) : "f"(lb), "f"(la));
}

// mma m16n8k8 tf32 -> f32
#define MMA_TF32(c, a0, a1, a2, a3, b0, b1)                                   \
    asm volatile(                                                             \
        "mma.sync.aligned.m16n8k8.row.col.f32.tf32.tf32.f32 "                 \
        "{%0,%1,%2,%3},{%4,%5,%6,%7},{%8,%9},{%0,%1,%2,%3};"                  \
        : "+f"((c)[0]), "+f"((c)[1]), "+f"((c)[2]), "+f"((c)[3])              \
        : "r"(a0), "r"(a1), "r"(a2), "r"(a3), "r"(b0), "r"(b1))

// mma m16n8k16 bf16 -> f32
#define MMA16816(c, a0, a1, a2, a3, b0, b1)                                   \
    asm volatile(                                                             \
        "mma.sync.aligned.m16n8k16.row.col.f32.bf16.bf16.f32 "                \
        "{%0,%1,%2,%3}, {%4,%5,%6,%7}, {%8,%9}, {%0,%1,%2,%3};"               \
        : "+f"((c)[0]), "+f"((c)[1]), "+f"((c)[2]), "+f"((c)[3])              \
        : "r"(a0), "r"(a1), "r"(a2), "r"(a3), "r"(b0), "r"(b1))

#define LDSM_X4(d0,d1,d2,d3,a)                                                \
    asm volatile("ldmatrix.sync.aligned.m8n8.x4.shared.b16 {%0,%1,%2,%3}, [%4];" \
        : "=r"(d0), "=r"(d1), "=r"(d2), "=r"(d3) : "r"(a))
#define LDSM_X4_T(d0,d1,d2,d3,a)                                              \
    asm volatile("ldmatrix.sync.aligned.m8n8.x4.trans.shared.b16 {%0,%1,%2,%3}, [%4];" \
        : "=r"(d0), "=r"(d1), "=r"(d2), "=r"(d3) : "r"(a))

#define ONESBF 0x3F803F80u

// ---------------------------------------------------------------------------
// Fused prep: RoPE tables + tf32 pre-rounding of x and the four W matrices.
// ---------------------------------------------------------------------------
__global__ void prep_kernel(const float* __restrict__ x,
                            const float* __restrict__ wq,
                            const float* __restrict__ wk,
                            const float* __restrict__ wv,
                            const float* __restrict__ wo)
{
    int gidx = blockIdx.x * 256 + threadIdx.x;

    if (gidx < Sn * 32) {        // RoPE tables
        int pos = gidx >> 5;
        int i   = gidx & 31;
        float inv = exp2f(-(float)i * 0.4152410118609203f);  // log2(10000)/32
        float ang = (float)pos * inv;
        float s, c;
        sincosf(ang, &s, &c);
        g_cos[gidx] = c;
        g_sin[gidx] = s;
    }

    int i4 = gidx * 4;
    const float* src;
    float* dst;
    int off;
    if (i4 < Mn * Dn) {
        src = x; dst = g_xr; off = i4;
    } else {
        int j = i4 - Mn * Dn;
        int w = j >> 20;
        off = j & ((1 << 20) - 1);
        src = (w == 0) ? wq : (w == 1) ? wk : (w == 2) ? wv : wo;
        dst = (w == 0) ? g_wqr : (w == 1) ? g_wkr : (w == 2) ? g_wvr : g_wor;
    }
    float4 v = *(const float4*)(src + off);
    v.x = tf32r(v.x); v.y = tf32r(v.y); v.z = tf32r(v.z); v.w = tf32r(v.w);
    *(float4*)(dst + off) = v;
}

// ---------------------------------------------------------------------------
// Raw-mma tf32 GEMM (R11 config: 128x128 tile, 2 CTAs/SM, 3-stage cp.async)
// ---------------------------------------------------------------------------
#define LDT3 36
#define TILE3 (128 * LDT3)
#define STG3  (2 * TILE3)
#define GSMEM (3 * STG3 * 4)        // 110592 bytes

// Q scale with log2(e) folded in (softmax done in base 2)
#define QSCALE 0.18033688011112043f

template<int MODE>
__global__ void __launch_bounds__(256, 2) gemm_mma(
    const float* __restrict__ A,
    const float* __restrict__ W0, const float* __restrict__ W1,
    const float* __restrict__ W2,
    const float* __restrict__ b0p, const float* __restrict__ b1p,
    const float* __restrict__ b2p,
    float* __restrict__ C)
{
    extern __shared__ float smem[];
    const uint32_t sb = smem_u32(smem);
    const int tid = threadIdx.x;
    const int wid = tid >> 5, lane = tid & 31;
    const int g = lane >> 2, tig = lane & 3;
    const int wm = wid & 3, wn = wid >> 2;
    const int m0 = blockIdx.y * 128;

    int wsel = 0, n0;
    const float* W;
    const float* bias;
    if (MODE == 1) {
        wsel = blockIdx.x >> 3;
        n0 = (blockIdx.x & 7) * 128;
        W    = (wsel == 0) ? W0 : (wsel == 1) ? W1 : W2;
        bias = (wsel == 0) ? b0p : (wsel == 1) ? b1p : b2p;
    } else {
        n0 = blockIdx.x * 128;
        W = W0; bias = b0p;
    }

    const int l8 = lane & 7;
    const int lh = (lane >> 3) & 1;
    const int lq = (lane >> 4) & 1;
    uint32_t aoff[2];
    #pragma unroll
    for (int mi = 0; mi < 2; ++mi)
        aoff[mi] = (uint32_t)((wm * 32 + mi * 16 + lh * 8 + l8) * 144 + lq * 16);
    uint32_t boff[4];
    #pragma unroll
    for (int j = 0; j < 4; ++j)
        boff[j] = (uint32_t)(TILE3 * 4 +
                  (wn * 64 + (2 * j + lq) * 8 + l8) * 144 + lh * 16);

    auto loadChunk = [&](int c) {
        const uint32_t abase = sb + (uint32_t)(c % 3) * (STG3 * 4);
        const uint32_t wbase = abase + TILE3 * 4;
        const float* Ab = A + (size_t)m0 * Dn + c * 32;
        const float* Wb = W + (size_t)n0 * Dn + c * 32;
        #pragma unroll
        for (int i = 0; i < 4; ++i) {
            int task = tid + i * 256;
            int row = task >> 3;
            int q   = task & 7;
            uint32_t off = (uint32_t)(row * 144 + q * 16);
            cpa16(abase + off, Ab + (size_t)row * Dn + q * 4);
            cpa16(wbase + off, Wb + (size_t)row * Dn + q * 4);
        }
        CP_COMMIT();
    };

    float acc[2][8][4];
    #pragma unroll
    for (int mi = 0; mi < 2; ++mi)
        #pragma unroll
        for (int nj = 0; nj < 8; ++nj)
            #pragma unroll
            for (int e = 0; e < 4; ++e) acc[mi][nj][e] = 0.0f;

    loadChunk(0); loadChunk(1);

    for (int c = 0; c < 32; ++c) {
        if (c + 1 < 32) CP_WAIT(1);
        else            CP_WAIT(0);
        __syncthreads();
        if (c + 2 < 32) loadChunk(c + 2);

        const uint32_t stb = sb + (uint32_t)(c % 3) * (STG3 * 4);

        #pragma unroll
        for (int k8 = 0; k8 < 4; ++k8) {
            const uint32_t kb = (uint32_t)k8 * 32;
            uint32_t a[2][4];
            LDSM_X4(a[0][0], a[0][1], a[0][2], a[0][3], stb + aoff[0] + kb);
            LDSM_X4(a[1][0], a[1][1], a[1][2], a[1][3], stb + aoff[1] + kb);
            #pragma unroll
            for (int j = 0; j < 4; ++j) {
                uint32_t b00, b01, b10, b11;
                LDSM_X4(b00, b01, b10, b11, stb + boff[j] + kb);
                MMA_TF32(acc[0][2*j],   a[0][0], a[0][1], a[0][2], a[0][3], b00, b01);
                MMA_TF32(acc[1][2*j],   a[1][0], a[1][1], a[1][2], a[1][3], b00, b01);
                MMA_TF32(acc[0][2*j+1], a[0][0], a[0][1], a[0][2], a[0][3], b10, b11);
                MMA_TF32(acc[1][2*j+1], a[1][0], a[1][1], a[1][2], a[1][3], b10, b11);
            }
        }
    }

    #pragma unroll
    for (int mi = 0; mi < 2; ++mi) {
        #pragma unroll
        for (int nj = 0; nj < 8; ++nj) {
            const int col_l = wn * 64 + nj * 8 + 2 * tig;
            #pragma unroll
            for (int e2 = 0; e2 < 2; ++e2) {
                const int row = m0 + wm * 32 + mi * 16 + g + e2 * 8;
                float v0 = acc[mi][nj][e2 * 2 + 0] + __ldg(&bias[col_l]);
                float v1 = acc[mi][nj][e2 * 2 + 1] + __ldg(&bias[col_l + 1]);
                if (MODE == 0) {
                    *(float2*)(C + (size_t)row * Dn + n0 + col_l) =
                        make_float2(v0, v1);
                } else {
                    if (wsel < 2) {
                        const int pos = row & (Sn - 1);
                        const int i0 = (col_l & 63) >> 1;
                        float cc = g_cos[pos * 32 + i0];
                        float ss = g_sin[pos * 32 + i0];
                        float o0 = v0 * cc - v1 * ss;
                        float o1 = v0 * ss + v1 * cc;
                        v0 = o0; v1 = o1;
                    }
                    if (wsel == 0) { v0 *= QSCALE; v1 *= QSCALE; }
                    uint32_t hh, ll;
                    split2(v0, v1, hh, ll);
                    const size_t idx = (size_t)row * Dn + n0 + col_l;
                    __nv_bfloat16* dh = (wsel == 0) ? g_qh : (wsel == 1) ? g_kh : g_vh;
                    __nv_bfloat16* dl = (wsel == 0) ? g_ql : (wsel == 1) ? g_kl : g_vl;
                    *(uint32_t*)(dh + idx) = hh;
                    *(uint32_t*)(dl + idx) = ll;
                }
            }
        }
    }
}

// ---------------------------------------------------------------------------
// Flash attention v7: v6 + warp-level skip of fully-masked tiles.
// A tile with j0 > (last row of this warp) contributes only masked entries
// (p=0, alpha=1) -> state provably unchanged; skip QK/softmax/PV.
// ---------------------------------------------------------------------------
#define ASTG 36864
#define ATT_SMEM (3 * ASTG)         // 110592

__global__ void __launch_bounds__(256, 2) attn7(const int* __restrict__ eff,
                                                float* __restrict__ Outp)
{
    extern __shared__ char sm[];
    const uint32_t sb = smem_u32(sm);

    const int t = threadIdx.x, w = t >> 5, lane = t & 31;
    const int g = lane >> 2, tig = lane & 3;
    const int part = lane >> 3, r8 = lane & 7;
    const int q0 = ((int)gridDim.x - 1 - (int)blockIdx.x) * 128;
    const int h = blockIdx.y, b = blockIdx.z;
    const int kend = Sn - eff[b];
    const size_t bofs = (size_t)b * Sn * Dn + h * HDn;

    const int row0 = q0 + w * 16 + g;
    const int row1 = row0 + 8;
    const int wlast = q0 + w * 16 + 15;      // last q-row this warp owns

    const uint32_t kbase = sb + (part < 2 ? 0u : 9216u)
                         + (uint32_t)r8 * 144 + (uint32_t)(part & 1) * 16;
    const uint32_t vbase = sb + 18432u + (part < 2 ? 0u : 9216u)
                         + (uint32_t)(part & 1) * 1152 + (uint32_t)r8 * 144;

    // --- Q fragments (hi/lo) in registers ---
    uint32_t qhf[4][4], qlf[4][4];
    {
        const __nv_bfloat16* bh = g_qh + bofs + (size_t)row0 * Dn;
        const __nv_bfloat16* bl = g_ql + bofs + (size_t)row0 * Dn;
        #pragma unroll
        for (int ks = 0; ks < 4; ++ks) {
            int d0 = ks * 16 + 2 * tig;
            qhf[ks][0] = *(const uint32_t*)(bh + d0);
            qhf[ks][1] = *(const uint32_t*)(bh + 8 * (size_t)Dn + d0);
            qhf[ks][2] = *(const uint32_t*)(bh + d0 + 8);
            qhf[ks][3] = *(const uint32_t*)(bh + 8 * (size_t)Dn + d0 + 8);
            qlf[ks][0] = *(const uint32_t*)(bl + d0);
            qlf[ks][1] = *(const uint32_t*)(bl + 8 * (size_t)Dn + d0);
            qlf[ks][2] = *(const uint32_t*)(bl + d0 + 8);
            qlf[ks][3] = *(const uint32_t*)(bl + 8 * (size_t)Dn + d0 + 8);
        }
    }

    float oc[8][4];
    #pragma unroll
    for (int n = 0; n < 8; ++n) { oc[n][0]=0.f; oc[n][1]=0.f; oc[n][2]=0.f; oc[n][3]=0.f; }
    float m0r = -1e30f, m1r = -1e30f, l0r = 0.f, l1r = 0.f;

    const int klimit = min(q0 + 128, kend);
    const int nt = (klimit + 63) >> 6;

    auto loadTile = [&](int tile) {
        const uint32_t base = sb + (uint32_t)(tile % 3) * ASTG;
        const size_t go = bofs + (size_t)(tile * 64) * Dn;
        const __nv_bfloat16* srcs[4] = { g_kh + go, g_kl + go, g_vh + go, g_vl + go };
        #pragma unroll
        for (int i = 0; i < 8; ++i) {
            const int arr = i >> 1;
            const int c2 = t + (i & 1) * 256;     // 0..511
            const int kr = c2 >> 3, q = c2 & 7;
            cpa16(base + (uint32_t)arr * 9216 + (uint32_t)kr * 144 + (uint32_t)q * 16,
                  srcs[arr] + (size_t)kr * Dn + q * 8);
        }
        CP_COMMIT();
    };

    loadTile(0);
    if (nt > 1) loadTile(1);

    for (int tile = 0; tile < nt; ++tile) {
        const int j0 = tile * 64;
        if (tile + 1 < nt) CP_WAIT(1);
        else               CP_WAIT(0);
        __syncthreads();
        if (tile + 2 < nt) loadTile(tile + 2);

        // Warp-uniform skip: tile entirely above this warp's rows.
        if (j0 > wlast) continue;

        const uint32_t stoff = (uint32_t)(tile % 3) * ASTG;

        // --- S = Q K^T (bf16x3) via ldmatrix ---
        float sc[8][4];
        #pragma unroll
        for (int n = 0; n < 8; ++n) {
            float c[4] = {0.f, 0.f, 0.f, 0.f};
            const uint32_t ka = kbase + stoff + (uint32_t)n * 1152;
            #pragma unroll
            for (int ks = 0; ks < 4; ++ks) {
                uint32_t b0h, b1h, b0l, b1l;
                LDSM_X4(b0h, b1h, b0l, b1l, ka + (uint32_t)ks * 32);
                MMA16816(c, qhf[ks][0], qhf[ks][1], qhf[ks][2], qhf[ks][3], b0h, b1h);
                MMA16816(c, qhf[ks][0], qhf[ks][1], qhf[ks][2], qhf[ks][3], b0l, b1l);
                MMA16816(c, qlf[ks][0], qlf[ks][1], qlf[ks][2], qlf[ks][3], b0h, b1h);
            }
            sc[n][0] = c[0]; sc[n][1] = c[1]; sc[n][2] = c[2]; sc[n][3] = c[3];
        }

        // --- mask (skipped for interior tiles; warp-uniform test) ---
        const bool interior = (j0 + 63 <= q0 + w * 16) && (j0 + 64 <= kend);
        if (!interior) {
            #pragma unroll
            for (int n = 0; n < 8; ++n) {
                int col = j0 + n * 8 + 2 * tig;
                sc[n][0] = (col     <= row0 && col     < kend) ? sc[n][0] : -1e30f;
                sc[n][1] = (col + 1 <= row0 && col + 1 < kend) ? sc[n][1] : -1e30f;
                sc[n][2] = (col     <= row1 && col     < kend) ? sc[n][2] : -1e30f;
                sc[n][3] = (col + 1 <= row1 && col + 1 < kend) ? sc[n][3] : -1e30f;
            }
        }

        // --- register online softmax (base-2); row max via shfl ---
        float mx0 = -1e30f, mx1 = -1e30f;
        #pragma unroll
        for (int n = 0; n < 8; ++n) {
            mx0 = fmaxf(mx0, fmaxf(sc[n][0], sc[n][1]));
            mx1 = fmaxf(mx1, fmaxf(sc[n][2], sc[n][3]));
        }
        mx0 = fmaxf(mx0, __shfl_xor_sync(0xffffffffu, mx0, 1));
        mx0 = fmaxf(mx0, __shfl_xor_sync(0xffffffffu, mx0, 2));
        mx1 = fmaxf(mx1, __shfl_xor_sync(0xffffffffu, mx1, 1));
        mx1 = fmaxf(mx1, __shfl_xor_sync(0xffffffffu, mx1, 2));

        float nm0 = fmaxf(m0r, mx0), nm1 = fmaxf(m1r, mx1);
        float al0 = ex2(m0r - nm0), al1 = ex2(m1r - nm1);
        m0r = nm0; m1r = nm1;

        #pragma unroll
        for (int n = 0; n < 8; ++n) {
            sc[n][0] = ex2(sc[n][0] - nm0);
            sc[n][1] = ex2(sc[n][1] - nm0);
            sc[n][2] = ex2(sc[n][2] - nm1);
            sc[n][3] = ex2(sc[n][3] - nm1);
        }

        #pragma unroll
        for (int n = 0; n < 8; ++n) {
            oc[n][0] *= al0; oc[n][1] *= al0;
            oc[n][2] *= al1; oc[n][3] *= al1;
        }

        // --- O += P V (bf16x3) + row-sum via ones-column mma ---
        float ps[4] = {0.f, 0.f, 0.f, 0.f};
        #pragma unroll
        for (int ks = 0; ks < 4; ++ks) {
            uint32_t a0h, a1h, a2h, a3h, a0l, a1l, a2l, a3l;
            split2(sc[2*ks][0],   sc[2*ks][1],   a0h, a0l);
            split2(sc[2*ks][2],   sc[2*ks][3],   a1h, a1l);
            split2(sc[2*ks+1][0], sc[2*ks+1][1], a2h, a2l);
            split2(sc[2*ks+1][2], sc[2*ks+1][3], a3h, a3l);
            MMA16816(ps, a0h, a1h, a2h, a3h, ONESBF, ONESBF);
            MMA16816(ps, a0l, a1l, a2l, a3l, ONESBF, ONESBF);
            const uint32_t va = vbase + stoff + (uint32_t)ks * 2304;
            #pragma unroll
            for (int n = 0; n < 8; ++n) {
                uint32_t b0h, b1h, b0l, b1l;
                LDSM_X4_T(b0h, b1h, b0l, b1l, va + (uint32_t)n * 16);
                MMA16816(oc[n], a0h, a1h, a2h, a3h, b0h, b1h);
                MMA16816(oc[n], a0h, a1h, a2h, a3h, b0l, b1l);
                MMA16816(oc[n], a0l, a1l, a2l, a3l, b0h, b1h);
            }
        }
        l0r = l0r * al0 + ps[0];
        l1r = l1r * al1 + ps[2];
    }

    // --- epilogue: normalize + tf32-round + store ---
    float invA = 1.f / l0r;
    float invB = 1.f / l1r;
    float* Ob = Outp + bofs + (size_t)row0 * Dn;
    #pragma unroll
    for (int n = 0; n < 8; ++n) {
        int cc = n * 8 + 2 * tig;
        *(float2*)&Ob[cc] =
            make_float2(tf32r(oc[n][0] * invA), tf32r(oc[n][1] * invA));
        *(float2*)(Ob + 8 * (size_t)Dn + cc) =
            make_float2(tf32r(oc[n][2] * invB), tf32r(oc[n][3] * invB));
    }
}

// ---------------------------------------------------------------------------
extern "C" void kernel_launch(void* const* d_in, const int* in_sizes, int n_in,
                              void* d_out, int out_size)
{
    const float* x   = (const float*)d_in[0];
    const int*   eff = (const int*)d_in[1];
    const float* Wq  = (const float*)d_in[2];
    const float* bq  = (const float*)d_in[3];
    const float* Wk  = (const float*)d_in[4];
    const float* bk  = (const float*)d_in[5];
    const float* Wv  = (const float*)d_in[6];
    const float* bv  = (const float*)d_in[7];
    const float* Wo  = (const float*)d_in[8];
    const float* bo  = (const float*)d_in[9];
    float* out = (float*)d_out;

    float *att, *xr, *wqr, *wkr, *wvr, *wor;
    cudaGetSymbolAddress((void**)&att, g_att);
    cudaGetSymbolAddress((void**)&xr,  g_xr);
    cudaGetSymbolAddress((void**)&wqr, g_wqr);
    cudaGetSymbolAddress((void**)&wkr, g_wkr);
    cudaGetSymbolAddress((void**)&wvr, g_wvr);
    cudaGetSymbolAddress((void**)&wor, g_wor);

    cudaFuncSetAttribute(gemm_mma<0>,
                         cudaFuncAttributeMaxDynamicSharedMemorySize, GSMEM);
    cudaFuncSetAttribute(gemm_mma<1>,
                         cudaFuncAttributeMaxDynamicSharedMemorySize, GSMEM);
    cudaFuncSetAttribute(attn7,
                         cudaFuncAttributeMaxDynamicSharedMemorySize, ATT_SMEM);

    prep_kernel<<<(Mn * Dn + 4 * Dn * Dn) / 1024, 256>>>(x, Wq, Wk, Wv, Wo);

    // fused QKV projection (3 x 8 n-tiles x 32 m-tiles)
    gemm_mma<1><<<dim3(24, 32), 256, GSMEM>>>(xr, wqr, wkr, wvr,
                                              bq, bk, bv, nullptr);

    attn7<<<dim3(Sn / 128, Hn, Bn), 256, ATT_SMEM>>>(eff, att);

    // O projection
    gemm_mma<0><<<dim3(8, 32), 256, GSMEM>>>(att, wor, nullptr, nullptr,
                                             bo, nullptr, nullptr, out);
}